// round 7
// baseline (speedup 1.0000x reference)
#include <cuda_runtime.h>
#include <cstdint>

#define B_   1024
#define T_   64
#define D_   512
#define H_   512
#define G4_  2048   // 4*H

// ---------------- device scratch (no allocation allowed) --------------------
__device__ float g_xp[(size_t)T_ * B_ * G4_];   // 512 MB: x@W + bias, [T][B][4H]
__device__ float g_xt[(size_t)T_ * D_ * B_];    // 128 MB: tf32-rounded X, [T][D][B]
__device__ float g_w32[(size_t)D_ * G4_];       // 4 MB: tf32-rounded kernel [D][4H]
__device__ float g_u32[(size_t)H_ * G4_];       // 4 MB: tf32-rounded recurrent kernel
__device__ float g_hT[2][(size_t)H_ * B_];      // 2x2 MB: rounded h, TRANSPOSED [H][B], ping-pong
__device__ unsigned g_bar[16];                  // per-by-group step barrier counters

// ---------------- helpers ---------------------------------------------------
__device__ __forceinline__ uint32_t f2tf32(float f) {
    uint32_t r;
    asm("cvt.rna.tf32.f32 %0, %1;" : "=r"(r) : "f"(f));
    return r;
}
__device__ __forceinline__ float rtf(float f) { return __uint_as_float(f2tf32(f)); }

__device__ __forceinline__ void mma8(float* c, const uint32_t* a, const uint32_t* b) {
    asm volatile(
        "mma.sync.aligned.m16n8k8.row.col.f32.tf32.tf32.f32 "
        "{%0,%1,%2,%3}, {%4,%5,%6,%7}, {%8,%9}, {%0,%1,%2,%3};\n"
        : "+f"(c[0]), "+f"(c[1]), "+f"(c[2]), "+f"(c[3])
        : "r"(a[0]), "r"(a[1]), "r"(a[2]), "r"(a[3]),
          "r"(b[0]), "r"(b[1]));
}

__device__ __forceinline__ float sigm(float x) { return 1.0f / (1.0f + __expf(-x)); }
__device__ __forceinline__ float tanh_(float x) { return 1.0f - 2.0f / (__expf(2.0f * x) + 1.0f); }

__device__ __forceinline__ void cp16(uint32_t s, const void* g) {
    asm volatile("cp.async.cg.shared.global [%0], [%1], 16;\n" :: "r"(s), "l"(g));
}
__device__ __forceinline__ void cpcommit() { asm volatile("cp.async.commit_group;\n"); }
template<int N> __device__ __forceinline__ void cpwait() {
    asm volatile("cp.async.wait_group %0;\n" :: "n"(N));
}

// ---------------- prep kernels ----------------------------------------------
__global__ void round_wu(const float* __restrict__ W, const float* __restrict__ U) {
    const int i = blockIdx.x * blockDim.x + threadIdx.x;   // D_*G4_ = 1M each
    g_w32[i] = rtf(W[i]);
    g_u32[i] = rtf(U[i]);
}

// X[b][t][k] -> g_xt[t][k][b], rounded to tf32
__global__ void prep_xt(const float* __restrict__ X) {
    __shared__ float tile[32][33];
    const int t = blockIdx.z, k0 = blockIdx.x * 32, b0 = blockIdx.y * 32;
    const int tx = threadIdx.x, ty = threadIdx.y;
#pragma unroll
    for (int i = 0; i < 4; i++)
        tile[ty + i * 8][tx] = X[((size_t)(b0 + ty + i * 8) * T_ + t) * D_ + k0 + tx];
    __syncthreads();
#pragma unroll
    for (int i = 0; i < 4; i++)
        g_xt[((size_t)t * D_ + k0 + ty + i * 8) * B_ + b0 + tx] = rtf(tile[tx][ty + i * 8]);
}

__global__ void zero_state() {
    const int i = blockIdx.x * blockDim.x + threadIdx.x;   // B_*H_
    g_hT[0][i] = 0.0f;
    g_hT[1][i] = 0.0f;
    if (i < 16) g_bar[i] = 0u;
}

// ---------------- stage 1: pipelined tf32 GEMM (unchanged from R5) ----------
// XP = Xperm @ W + bias, tiles 128x128, grid (16, 512)
__global__ void __launch_bounds__(256, 2)
gemm_x(const float* __restrict__ bias)
{
    constexpr int AROW = 136, BROW = 136;
    constexpr int STW  = 16 * AROW + 16 * BROW;

    extern __shared__ __align__(16) uint32_t sm[];
    const uint32_t sbase = (uint32_t)__cvta_generic_to_shared(sm);

    const int tid = threadIdx.x;
    const int bx = blockIdx.x, by = blockIdx.y;

    const int tt = by >> 3;
    const float* Abase = g_xt + (size_t)tt * D_ * B_ + (by & 7) * 128;

    uint32_t offA[2];
    const float* aG[2];
#pragma unroll
    for (int c = 0; c < 2; c++) {
        const int q = tid + c * 256;
        const int k = q >> 5, m4 = (q & 31) * 4;
        offA[c] = (uint32_t)(k * AROW + m4);
        aG[c]   = Abase + (size_t)k * B_ + m4;
    }
    uint32_t offB[2];
    const float* bG[2];
#pragma unroll
    for (int c = 0; c < 2; c++) {
        const int q = tid + c * 256;
        const int k = q >> 5, m4 = (q & 31) * 4;
        offB[c] = (uint32_t)(16 * AROW + k * BROW + m4);
        bG[c] = g_w32 + (size_t)k * G4_ + bx * 128 + m4;
    }

    const int warp = tid >> 5, lane = tid & 31;
    const int wm = warp >> 2, wn = warp & 3;
    const int gq = lane >> 2, tq = lane & 3;

    float acc[4][4][4] = {};

    auto ISSUE = [&](int kt, int s) {
#pragma unroll
        for (int c = 0; c < 2; c++)
            cp16(sbase + (uint32_t)(s * STW + offA[c]) * 4u, aG[c] + (size_t)kt * 16 * B_);
#pragma unroll
        for (int c = 0; c < 2; c++)
            cp16(sbase + (uint32_t)(s * STW + offB[c]) * 4u, bG[c] + (size_t)kt * 16 * G4_);
    };

    ISSUE(0, 0); cpcommit();
    ISSUE(1, 1); cpcommit();

    for (int kt = 0; kt < D_ / 16; kt++) {
        cpwait<1>();
        __syncthreads();
        if (kt + 2 < D_ / 16) ISSUE(kt + 2, (kt + 2) % 3);
        cpcommit();

        const uint32_t* As  = sm + (kt % 3) * STW;
        const uint32_t* Bsm = As + 16 * AROW;
#pragma unroll
        for (int k8 = 0; k8 < 16; k8 += 8) {
            uint32_t afr[4][4], bfr[4][2];
#pragma unroll
            for (int mf = 0; mf < 4; mf++) {
                const int r0 = wm * 64 + mf * 16 + gq;
                afr[mf][0] = As[(k8 + tq) * AROW + r0];
                afr[mf][1] = As[(k8 + tq) * AROW + r0 + 8];
                afr[mf][2] = As[(k8 + tq + 4) * AROW + r0];
                afr[mf][3] = As[(k8 + tq + 4) * AROW + r0 + 8];
            }
#pragma unroll
            for (int nf = 0; nf < 4; nf++) {
                const int c0 = wn * 32 + nf * 8 + gq;
                bfr[nf][0] = Bsm[(k8 + tq) * BROW + c0];
                bfr[nf][1] = Bsm[(k8 + tq + 4) * BROW + c0];
            }
#pragma unroll
            for (int mf = 0; mf < 4; mf++)
#pragma unroll
                for (int nf = 0; nf < 4; nf++)
                    mma8(acc[mf][nf], afr[mf], bfr[nf]);
        }
    }
    __syncthreads();

    const int n0 = bx * 128;
#pragma unroll
    for (int mf = 0; mf < 4; mf++)
#pragma unroll
        for (int nf = 0; nf < 4; nf++) {
            const int row = by * 128 + wm * 64 + mf * 16 + gq;   // = t*B_ + b
            const int col = n0 + wn * 32 + nf * 8 + tq * 2;
            const float b0v = bias[col], b1v = bias[col + 1];
            float2 v0 = make_float2(acc[mf][nf][0] + b0v, acc[mf][nf][1] + b1v);
            float2 v1 = make_float2(acc[mf][nf][2] + b0v, acc[mf][nf][3] + b1v);
            *(float2*)&g_xp[(size_t)row * G4_ + col] = v0;
            *(float2*)&g_xp[(size_t)(row + 8) * G4_ + col] = v1;
        }
}

// ---------------- stage 2: persistent recurrent kernel ----------------------
// grid (16, 16): bx = 32-hid slice, by = 64-batch slice. All 64 steps inside.
// Per-by-group spin barrier between steps; c lives in registers; xp tile
// prefetched into smem during the mainloop.
__global__ void __launch_bounds__(256, 2)
lstm_rec(float* __restrict__ out)
{
    constexpr int AROW = 72, BROW = 136;
    constexpr int STW  = 16 * AROW + 16 * BROW;   // 3328 words
    constexpr int XPW  = 3 * STW;                 // xp smem offset (words) = 9984
    constexpr int XROW = 132;                     // xp row stride (pad: kills LDS conflicts)

    extern __shared__ __align__(16) uint32_t sm[];
    const uint32_t sbase = (uint32_t)__cvta_generic_to_shared(sm);
    const float* xp_sm = (const float*)sm + XPW;

    const int tid = threadIdx.x;
    const int bx = blockIdx.x, by = blockIdx.y;

    // ---- A (h) loader: 1 chunk per thread
    const int ka  = tid >> 4;               // 0..15
    const int am4 = (tid & 15) * 4;         // 0..60
    const uint32_t offA = (uint32_t)(ka * AROW + am4);
    const size_t   aoff = (size_t)ka * B_ + by * 64 + am4;

    // ---- B (U) loader: 2 chunks per thread (gate-major cols)
    uint32_t offB[2];
    const float* bG[2];
#pragma unroll
    for (int c = 0; c < 2; c++) {
        const int q = tid + c * 256;
        const int k = q >> 5, m4 = (q & 31) * 4;
        offB[c] = (uint32_t)(16 * AROW + k * BROW + m4);
        const int gate = m4 >> 5, hid = m4 & 31;
        bG[c] = g_u32 + (size_t)k * G4_ + gate * H_ + bx * 32 + hid;
    }

    // ---- xp loader: 8 groups x 16B per thread covers 64x128 tile
    const int xr = tid >> 5;                // row 0..7 (plus 8*g)
    const int xc = (tid & 31) * 4;          // col 0..124
    const size_t xsrc0 = ((size_t)(by * 64 + xr)) * G4_
                       + (xc >> 5) * H_ + bx * 32 + (xc & 31);

    const int warp = tid >> 5, lane = tid & 31;
    const int wm = warp >> 2, wn = warp & 3;
    const int gq = lane >> 2, tq = lane & 3;
    const int hidl = wn * 8 + tq * 2;

    float cst[2][2][2] = {};                // cell state, registers only

    for (int t = 0; t < T_; t++) {
        const float* hbase = g_hT[t & 1];
        float*       hW    = g_hT[(t + 1) & 1];
        const size_t xstep = (size_t)t * B_ * G4_;

        float acc[2][4][4] = {};

        auto ISSUE = [&](int kt) {
            const uint32_t sb = sbase + (uint32_t)((kt % 3) * STW) * 4u;
            cp16(sb + offA * 4u, hbase + aoff + (size_t)kt * 16 * B_);
#pragma unroll
            for (int c = 0; c < 2; c++)
                cp16(sb + offB[c] * 4u, bG[c] + (size_t)kt * 16 * G4_);
            if (kt < 8)
                cp16(sbase + (uint32_t)(XPW + (xr + 8 * kt) * XROW + xc) * 4u,
                     g_xp + xstep + xsrc0 + (size_t)(8 * kt) * G4_);
        };

        ISSUE(0); cpcommit();
        ISSUE(1); cpcommit();

        for (int kt = 0; kt < H_ / 16; kt++) {
            cpwait<1>();
            __syncthreads();
            if (kt + 2 < H_ / 16) ISSUE(kt + 2);
            cpcommit();

            const uint32_t* As  = sm + (kt % 3) * STW;
            const uint32_t* Bsm = As + 16 * AROW;
#pragma unroll
            for (int k8 = 0; k8 < 16; k8 += 8) {
                uint32_t afr[2][4], bfr[4][2];
#pragma unroll
                for (int mf = 0; mf < 2; mf++) {
                    const int r0 = wm * 32 + mf * 16 + gq;
                    afr[mf][0] = As[(k8 + tq) * AROW + r0];
                    afr[mf][1] = As[(k8 + tq) * AROW + r0 + 8];
                    afr[mf][2] = As[(k8 + tq + 4) * AROW + r0];
                    afr[mf][3] = As[(k8 + tq + 4) * AROW + r0 + 8];
                }
#pragma unroll
                for (int nf = 0; nf < 4; nf++) {
                    const int c0 = nf * 32 + wn * 8 + gq;
                    bfr[nf][0] = Bsm[(k8 + tq) * BROW + c0];
                    bfr[nf][1] = Bsm[(k8 + tq + 4) * BROW + c0];
                }
#pragma unroll
                for (int mf = 0; mf < 2; mf++)
#pragma unroll
                    for (int nf = 0; nf < 4; nf++)
                        mma8(acc[mf][nf], afr[mf], bfr[nf]);
            }
        }

        // ---- fused LSTM cell epilogue (xp from smem, c in registers)
#pragma unroll
        for (int mf = 0; mf < 2; mf++) {
#pragma unroll
            for (int rh = 0; rh < 2; rh++) {
                const int rl = wm * 32 + mf * 16 + rh * 8 + gq;   // local batch row
                float z[4][2];
#pragma unroll
                for (int g = 0; g < 4; g++) {
                    z[g][0] = acc[mf][g][rh * 2 + 0] + xp_sm[rl * XROW + g * 32 + hidl];
                    z[g][1] = acc[mf][g][rh * 2 + 1] + xp_sm[rl * XROW + g * 32 + hidl + 1];
                }
                float2 hh;
                {
                    const float ii = sigm(z[0][0]), ff = sigm(z[1][0]);
                    const float gg = tanh_(z[2][0]), oo = sigm(z[3][0]);
                    cst[mf][rh][0] = ff * cst[mf][rh][0] + ii * gg;
                    hh.x = oo * tanh_(cst[mf][rh][0]);
                }
                {
                    const float ii = sigm(z[0][1]), ff = sigm(z[1][1]);
                    const float gg = tanh_(z[2][1]), oo = sigm(z[3][1]);
                    cst[mf][rh][1] = ff * cst[mf][rh][1] + ii * gg;
                    hh.y = oo * tanh_(cst[mf][rh][1]);
                }
                const int r = by * 64 + rl;
                *(float2*)&out[((size_t)r * T_ + t) * H_ + bx * 32 + hidl] = hh;
                hW[(size_t)(bx * 32 + hidl) * B_ + r]     = rtf(hh.x);
                hW[(size_t)(bx * 32 + hidl + 1) * B_ + r] = rtf(hh.y);
            }
        }

        // ---- per-by-group step barrier (16 CTAs)
        __syncthreads();
        if (tid == 0) {
            __threadfence();
            atomicAdd(&g_bar[by], 1u);
            const unsigned tgt = 16u * (unsigned)(t + 1);
            unsigned v;
            do {
                asm volatile("ld.acquire.gpu.u32 %0, [%1];"
                             : "=r"(v) : "l"(&g_bar[by]) : "memory");
                if (v < tgt) __nanosleep(20);
            } while (v < tgt);
        }
        __syncthreads();
    }
}

// ---------------- launch -----------------------------------------------------
extern "C" void kernel_launch(void* const* d_in, const int* in_sizes, int n_in,
                              void* d_out, int out_size)
{
    const float* X    = (const float*)d_in[0];   // [B, T, D]
    const float* W    = (const float*)d_in[1];   // [D, 4H]
    const float* U    = (const float*)d_in[2];   // [H, 4H]
    const float* bias = (const float*)d_in[3];   // [4H]
    float* out = (float*)d_out;                  // [B, T, H]

    constexpr int SM0 = 3 * (16 * 136 + 16 * 136) * 4;             // 52224 B
    constexpr int SM1 = (3 * (16 * 72 + 16 * 136) + 64 * 132) * 4; // 73728 B
    cudaFuncSetAttribute(gemm_x,   cudaFuncAttributeMaxDynamicSharedMemorySize, SM0);
    cudaFuncSetAttribute(lstm_rec, cudaFuncAttributeMaxDynamicSharedMemorySize, SM1);

    round_wu<<<(D_ * G4_) / 256, 256>>>(W, U);
    prep_xt<<<dim3(D_ / 32, B_ / 32, T_), dim3(32, 8)>>>(X);
    zero_state<<<(B_ * H_) / 256, 256>>>();

    // Stage 1: input projection (128x128 tiles)
    gemm_x<<<dim3(G4_ / 128, (T_ * B_) / 128), 256, SM0>>>(bias);

    // Stage 2: single persistent kernel runs all 64 recurrent steps
    lstm_rec<<<dim3(16, 16), 256, SM1>>>(out);
}